// round 4
// baseline (speedup 1.0000x reference)
#include <cuda_runtime.h>
#include <cstdint>

#define N_BATCH 8
#define K_ANCH  9
#define Hdim    120
#define Wdim    120
#define HW      (Hdim*Wdim)
#define TOT     (HW*K_ANCH)       /* 129600 */
#define PRE     3000
#define POST    300
#define CAND_MAX 8192
#define NBUCKET  4096
#define NT       512              /* scan block size */
#define SLOTS    6                /* boxes per thread: 512*6 = 3072 >= 3000 */

// ---------------- scratch (static device globals; no allocation) ------------
__device__ int    g_topk_idx[N_BATCH*PRE];
__device__ float  g_topk_score[N_BATCH*PRE];
__device__ float4 g_boxes[N_BATCH*PRE];
__device__ float  g_selscore[N_BATCH*POST];

// monotone float->uint key (descending floats -> descending uints)
__device__ __forceinline__ unsigned int fkey(float x) {
    unsigned int u = __float_as_uint(x);
    return (u & 0x80000000u) ? ~u : (u | 0x80000000u);
}
__device__ __forceinline__ float fkey_inv(unsigned int k) {
    return (k & 0x80000000u) ? __uint_as_float(k ^ 0x80000000u)
                             : __uint_as_float(~k);
}

// ---------------- Stage 1: per-batch exact top-3000 -------------------------
extern "C" __global__ void __launch_bounds__(1024)
topk_kernel(const float* __restrict__ cls) {
    extern __shared__ unsigned long long s_cand[];   // 8192 * 8B = 64KB
    __shared__ unsigned int hist[NBUCKET];           // 16KB
    __shared__ unsigned int psum[1024];              // 4KB
    __shared__ unsigned int s_B;
    __shared__ unsigned int s_cnt;

    const int n   = blockIdx.x;
    const int tid = threadIdx.x;
    const float* sc = cls + (size_t)n * TOT;

    for (int b = tid; b < NBUCKET; b += 1024) hist[b] = 0;
    if (tid == 0) s_cnt = 0;
    __syncthreads();

    for (int i = tid; i < TOT; i += 1024)
        atomicAdd(&hist[fkey(sc[i]) >> 20], 1u);
    __syncthreads();

    psum[tid] = hist[4*tid] + hist[4*tid+1] + hist[4*tid+2] + hist[4*tid+3];
    __syncthreads();

    if (tid == 0) {
        unsigned int acc = 0;
        int S = 0;
        for (int s = 31; s >= 0; --s) {
            unsigned int q = 0;
            for (int t = 0; t < 32; ++t) q += psum[s*32 + t];
            if (acc + q >= PRE) { S = s; break; }
            acc += q;
        }
        int Pb = S*32;
        for (int t = 31; t >= 0; --t) {
            unsigned int q = psum[S*32 + t];
            if (acc + q >= PRE) { Pb = S*32 + t; break; }
            acc += q;
        }
        unsigned int B = (unsigned int)(Pb*4);
        for (int b = 3; b >= 0; --b) {
            unsigned int q = hist[Pb*4 + b];
            if (acc + q >= PRE) { B = (unsigned int)(Pb*4 + b); break; }
            acc += q;
        }
        s_B = B;
    }
    __syncthreads();

    const unsigned int thr = s_B << 20;
    for (int i = tid; i < TOT; i += 1024) {
        unsigned int k = fkey(sc[i]);
        if (k >= thr) {
            unsigned int pos = atomicAdd(&s_cnt, 1u);
            if (pos < CAND_MAX)
                s_cand[pos] = ((unsigned long long)k << 32) |
                              (unsigned int)(~(unsigned int)i);
        }
    }
    __syncthreads();

    const unsigned int cnt = s_cnt;               // guaranteed >= PRE
    const int S_sort = (cnt <= 4096u) ? 4096 : 8192;
    for (int i = (int)cnt + tid; i < S_sort; i += 1024) s_cand[i] = 0ull;
    __syncthreads();

    // bitonic sort, descending on u64 (ties: smaller idx first via ~idx)
    for (int k = 2; k <= S_sort; k <<= 1) {
        for (int j = k >> 1; j > 0; j >>= 1) {
            for (int i = tid; i < S_sort; i += 1024) {
                int ixj = i ^ j;
                if (ixj > i) {
                    unsigned long long a = s_cand[i], b = s_cand[ixj];
                    bool dir = (i & k) != 0;
                    if ((a < b) != dir) { s_cand[i] = b; s_cand[ixj] = a; }
                }
            }
            __syncthreads();
        }
    }

    for (int r = tid; r < PRE; r += 1024) {
        unsigned long long c = s_cand[r];
        unsigned int key = (unsigned int)(c >> 32);
        int idx = (int)(~(unsigned int)(c & 0xFFFFFFFFull));
        g_topk_idx[n*PRE + r]   = idx;
        g_topk_score[n*PRE + r] = fkey_inv(key);
    }
}

// ---------------- Stage 2: gather-compute selected boxes --------------------
extern "C" __global__ void boxes_kernel(const float* __restrict__ deltas) {
    int g = blockIdx.x*blockDim.x + threadIdx.x;
    if (g >= N_BATCH*PRE) return;
    const int n = g / PRE;
    const int o = g_topk_idx[g];

    const int kk = o % K_ANCH;
    const int t0 = o / K_ANCH;
    const int ww = t0 % Wdim;
    const int hh = t0 / Wdim;

    const float ratios_[3] = {0.5f, 1.0f, 2.0f};
    const float scales_[3] = {8.0f, 16.0f, 32.0f};

    float v[4];
#pragma unroll
    for (int jj = 0; jj < 4; ++jj) {
        int f  = ((kk*4 + jj)*Hdim + hh)*Wdim + ww;
        int j  = f & 3;
        int r1 = f >> 2;
        int k  = r1 % K_ANCH;
        int r2 = r1 / K_ANCH;
        int w  = r2 % Wdim;
        int h  = r2 / Wdim;

        float sr  = __fsqrt_rn(ratios_[k/3]);
        float wsz = __fdiv_rn(__fmul_rn(16.0f, scales_[k%3]), sr);
        float hsz = __fmul_rn(__fmul_rn(16.0f, scales_[k%3]), sr);
        float cx  = __fmul_rn(__fadd_rn((float)w, 0.5f), 16.0f);
        float cy  = __fmul_rn(__fadd_rn((float)h, 0.5f), 16.0f);

        float a;
        if      (j == 0) a = __fsub_rn(cx, __fmul_rn(0.5f, wsz));
        else if (j == 1) a = __fsub_rn(cy, __fmul_rn(0.5f, hsz));
        else if (j == 2) a = __fadd_rn(cx, __fmul_rn(0.5f, wsz));
        else             a = __fadd_rn(cy, __fmul_rn(0.5f, hsz));

        float d   = deltas[((size_t)n*36 + (k*4 + j))*HW + h*Wdim + w];
        float val = __fadd_rn(a, d);
        v[jj] = fminf(fmaxf(val, 0.0f), 1919.0f);
    }
    g_boxes[g] = make_float4(v[0], v[1], v[2], v[3]);
}

// ---------------- Stage 3+4 fused: register-resident dynamic NMS ------------
// One 512-thread block per batch. Thread t owns boxes t, t+512, ..., t+2560
// in registers. Per kept box: publish via smem, everyone kills its own alive
// boxes by on-the-fly IoU (bitwise same as reference), REDUX.MIN + smem
// atomicMin finds the next survivor. No global memory in the loop.
extern "C" __global__ void __launch_bounds__(NT)
scan_kernel(float* __restrict__ out) {
    const int n = blockIdx.x;
    const int tid = threadIdx.x;
    __shared__ float4 s_box;
    __shared__ float  s_area;
    __shared__ int    s_next[2];      // ping-pong reduction slots
    __shared__ int    s_kept[POST];

    float4 bx[SLOTS];
    float  ar[SLOTS];
    bool   alive[SLOTS];
#pragma unroll
    for (int s = 0; s < SLOTS; ++s) {
        int i = tid + s*NT;
        if (i < PRE) {
            float4 b = g_boxes[n*PRE + i];
            bx[s] = b;
            ar[s] = __fmul_rn(__fadd_rn(__fsub_rn(b.z, b.x), 1.0f),
                              __fadd_rn(__fsub_rn(b.w, b.y), 1.0f));
            alive[s] = true;
        } else {
            bx[s] = make_float4(0,0,0,0); ar[s] = 0.0f; alive[s] = false;
        }
    }
    if (tid == 0) { s_next[0] = 0x7fffffff; s_next[1] = 0x7fffffff; }
    __syncthreads();

    int i_cur = 0;      // box 0 is always the first kept
    int nk = 0;
    while (true) {
        if (tid == 0) s_kept[nk] = i_cur;
        ++nk;
        if (nk >= POST) break;
        const int p = nk & 1;

        if (tid == (i_cur & (NT-1))) {          // owner publishes kept box
            int s = i_cur >> 9;                 // NT == 512
            s_box  = bx[s];
            s_area = ar[s];
            alive[s] = false;                   // consume it
        }
        __syncthreads();

        if (tid == 0) s_next[p ^ 1] = 0x7fffffff;   // reset other slot for
                                                    // next iteration (barrier-
                                                    // separated both ways)
        const float4 kb = s_box;
        const float  ka = s_area;
        int local_next = 0x7fffffff;
#pragma unroll
        for (int s = 0; s < SLOTS; ++s) {
            if (alive[s]) {
                float xx1 = fmaxf(kb.x, bx[s].x), yy1 = fmaxf(kb.y, bx[s].y);
                float xx2 = fminf(kb.z, bx[s].z), yy2 = fminf(kb.w, bx[s].w);
                float iw = fmaxf(__fadd_rn(__fsub_rn(xx2, xx1), 1.0f), 0.0f);
                float ih = fmaxf(__fadd_rn(__fsub_rn(yy2, yy1), 1.0f), 0.0f);
                float inter = __fmul_rn(iw, ih);
                float denom = __fsub_rn(__fadd_rn(ka, ar[s]), inter);
                if (__fdiv_rn(inter, denom) > 0.5f) {
                    alive[s] = false;
                } else {
                    local_next = min(local_next, tid + s*NT);
                }
            }
        }
        int wmin = __reduce_min_sync(0xffffffffu, local_next);
        if ((tid & 31) == 0) atomicMin(&s_next[p], wmin);
        __syncthreads();

        i_cur = s_next[p];
        if (i_cur == 0x7fffffff) break;
    }
    __syncthreads();

    for (int r = tid; r < POST; r += NT) {
        float sc = 0.0f, x1 = 0.0f, y1 = 0.0f, x2 = 0.0f, y2 = 0.0f;
        if (r < nk) {
            int i = s_kept[r];
            float4 b = g_boxes[n*PRE + i];
            x1 = b.x; y1 = b.y; x2 = b.z; y2 = b.w;
            sc = g_topk_score[n*PRE + i];
        }
        float* o = out + (size_t)(n*POST + r)*5;
        o[1] = x1; o[2] = y1; o[3] = x2; o[4] = y2;
        g_selscore[n*POST + r] = sc;
    }
}

// ---------------- Stage 5: score column = batch 7's selected scores ---------
extern "C" __global__ void final_kernel(float* __restrict__ out) {
    int g = blockIdx.x*blockDim.x + threadIdx.x;
    if (g >= N_BATCH*POST) return;
    int r = g % POST;
    out[(size_t)g*5] = g_selscore[7*POST + r];
}

// ---------------- launch -----------------------------------------------------
extern "C" void kernel_launch(void* const* d_in, const int* in_sizes, int n_in,
                              void* d_out, int out_size) {
    const float* cls;
    const float* deltas;
    if (in_sizes[0] == N_BATCH*K_ANCH*HW) {     // 1,036,800
        cls = (const float*)d_in[0]; deltas = (const float*)d_in[1];
    } else {
        cls = (const float*)d_in[1]; deltas = (const float*)d_in[0];
    }
    float* out = (float*)d_out;

    cudaFuncSetAttribute(topk_kernel,
                         cudaFuncAttributeMaxDynamicSharedMemorySize, 65536);

    topk_kernel<<<N_BATCH, 1024, 65536>>>(cls);
    boxes_kernel<<<(N_BATCH*PRE + 255)/256, 256>>>(deltas);
    scan_kernel<<<N_BATCH, NT>>>(out);
    final_kernel<<<(N_BATCH*POST + 255)/256, 256>>>(out);
}